// round 3
// baseline (speedup 1.0000x reference)
#include <cuda_runtime.h>
#include <cuda_bf16.h>
#include <math.h>

// Problem constants
#define BB 4
#define SS 1024
#define EE 1024
#define HH 16
#define DH 64
#define ROWS (BB*SS)           // 4096
#define LN_EPS 1e-5f

// ---------------- scratch (device globals; no allocation allowed) ----------------
__device__ float g_h   [ROWS*EE];                 // 16MB  ln1 out
__device__ float g_qkv [ROWS*3*EE];               // 48MB  qkv
__device__ float g_probs[(long long)BB*HH*SS*SS]; // 256MB probs
__device__ float g_att [ROWS*EE];                 // 16MB  attention out (B,S,H,DH)
__device__ float g_x1  [ROWS*EE];                 // 16MB  x + attproj
__device__ float g_h2  [ROWS*EE];                 // 16MB  ln2 out
__device__ float g_fc  [ROWS*4*EE];               // 64MB  gelu(fc)

// ---------------- LayerNorm: one block per row ----------------
__global__ void ln_kernel(const float* __restrict__ x,
                          const float* __restrict__ g,
                          const float* __restrict__ b,
                          float* __restrict__ out)
{
    long long row = blockIdx.x;
    const float* xr = x + row * EE;
    float* orow = out + row * EE;
    __shared__ float red[256];
    int tid = threadIdx.x;

    float s = 0.f;
    #pragma unroll
    for (int c = tid; c < EE; c += 256) s += xr[c];
    red[tid] = s; __syncthreads();
    for (int st = 128; st > 0; st >>= 1) { if (tid < st) red[tid] += red[tid+st]; __syncthreads(); }
    float mu = red[0] * (1.f/EE);
    __syncthreads();

    float v = 0.f;
    #pragma unroll
    for (int c = tid; c < EE; c += 256) { float d = xr[c] - mu; v += d*d; }
    red[tid] = v; __syncthreads();
    for (int st = 128; st > 0; st >>= 1) { if (tid < st) red[tid] += red[tid+st]; __syncthreads(); }
    float inv = rsqrtf(red[0] * (1.f/EE) + LN_EPS);
    __syncthreads();

    #pragma unroll
    for (int c = tid; c < EE; c += 256)
        orow[c] = (xr[c] - mu) * inv * g[c] + b[c];
}

// ---------------- generic tiled GEMM ----------------
// C[m,n] = alpha * sum_k A[m,k] * B(k,n)  (+bias[n]) (+resid[m,n]) (gelu) (causal mask)
// TRANSB=true : B stored [N,K] row-major -> B[n*ldb + k]
// TRANSB=false: B stored [K,N] row-major -> B[k*ldb + n]
// Batched via blockIdx.z = bb*Hdiv + hh with separate b/h strides.
// All dims must be multiples of the tile (true for every call here).
template<bool TRANSB>
__global__ __launch_bounds__(256)
void gemm_kernel(const float* __restrict__ Abase,
                 const float* __restrict__ Bbase,
                 float* __restrict__ Cbase,
                 const float* __restrict__ bias,
                 const float* __restrict__ resid,
                 int M, int N, int K,
                 int lda, int ldb, int ldc,
                 long long sAb, long long sAh,
                 long long sBb, long long sBh,
                 long long sCb, long long sCh,
                 int Hdiv, float alpha, int doGelu, int doMask)
{
    int z  = blockIdx.z;
    int bb = z / Hdiv, hh = z % Hdiv;
    const float* A  = Abase + (long long)bb*sAb + (long long)hh*sAh;
    const float* Bp = Bbase + (long long)bb*sBb + (long long)hh*sBh;
    float*       C  = Cbase + (long long)bb*sCb + (long long)hh*sCh;

    __shared__ float As[16][68];   // row stride 272B = 17*16B -> float4-aligned
    __shared__ float Bs[16][68];

    int tid = threadIdx.x;            // 256 threads
    int tx = tid & 15, ty = tid >> 4; // 16x16
    int m0 = blockIdx.y * 64, n0 = blockIdx.x * 64;

    float acc[4][4] = {};

    for (int k0 = 0; k0 < K; k0 += 16) {
        // A tile: 64 x 16 -> As[k][m]
        {
            int k = tid & 15, m = tid >> 4;
            #pragma unroll
            for (int r = 0; r < 4; r++) {
                int mm = m + r*16;
                As[k][mm] = A[(long long)(m0+mm)*lda + k0 + k];
            }
        }
        // B tile: 16 x 64 -> Bs[k][n]
        if (TRANSB) {
            int k = tid & 15, n = tid >> 4;
            #pragma unroll
            for (int r = 0; r < 4; r++) {
                int nn = n + r*16;
                Bs[k][nn] = Bp[(long long)(n0+nn)*ldb + k0 + k];
            }
        } else {
            int n = tid & 63, k = tid >> 6;
            #pragma unroll
            for (int r = 0; r < 4; r++) {
                int kk = k + r*4;
                Bs[kk][n] = Bp[(long long)(k0+kk)*ldb + n0 + n];
            }
        }
        __syncthreads();

        #pragma unroll
        for (int kk = 0; kk < 16; kk++) {
            float4 a4 = *reinterpret_cast<const float4*>(&As[kk][ty*4]);
            float4 b4 = *reinterpret_cast<const float4*>(&Bs[kk][tx*4]);
            float a[4] = {a4.x, a4.y, a4.z, a4.w};
            float bv[4] = {b4.x, b4.y, b4.z, b4.w};
            #pragma unroll
            for (int i = 0; i < 4; i++)
                #pragma unroll
                for (int j = 0; j < 4; j++)
                    acc[i][j] = fmaf(a[i], bv[j], acc[i][j]);
        }
        __syncthreads();
    }

    #pragma unroll
    for (int i = 0; i < 4; i++) {
        int m = m0 + ty*4 + i;
        #pragma unroll
        for (int j = 0; j < 4; j++) {
            int n = n0 + tx*4 + j;
            float c = acc[i][j] * alpha;
            if (bias)  c += bias[n];
            if (resid) c += resid[(long long)m*ldc + n];
            if (doGelu) {
                float xg = c;
                float t = tanhf(0.7978845608028654f * (xg + 0.044715f*xg*xg*xg));
                c = 0.5f * xg * (1.f + t);
            }
            if (doMask && n > m) c = -1e30f;   // causal: k > q
            C[(long long)m*ldc + n] = c;
        }
    }
}

// ---------------- softmax over last dim (1024), one block per row ----------------
__global__ void softmax_kernel(float* __restrict__ p)
{
    long long row = blockIdx.x;
    float* r = p + row * (long long)SS;
    __shared__ float red[256];
    int tid = threadIdx.x;

    float mx = -1e30f;
    #pragma unroll
    for (int c = tid; c < SS; c += 256) mx = fmaxf(mx, r[c]);
    red[tid] = mx; __syncthreads();
    for (int st = 128; st > 0; st >>= 1) { if (tid < st) red[tid] = fmaxf(red[tid], red[tid+st]); __syncthreads(); }
    mx = red[0]; __syncthreads();

    float sum = 0.f;
    #pragma unroll
    for (int c = tid; c < SS; c += 256) { float e = __expf(r[c] - mx); r[c] = e; sum += e; }
    red[tid] = sum; __syncthreads();
    for (int st = 128; st > 0; st >>= 1) { if (tid < st) red[tid] += red[tid+st]; __syncthreads(); }
    float inv = 1.f / red[0];
    __syncthreads();

    #pragma unroll
    for (int c = tid; c < SS; c += 256) r[c] *= inv;
}

// ---------------- att_weights = mean over heads of probs ----------------
__global__ void attw_kernel(const float* __restrict__ probs, float* __restrict__ out)
{
    long long idx = (long long)blockIdx.x * 256 + threadIdx.x;
    if (idx >= (long long)BB*SS*SS) return;
    long long b   = idx / ((long long)SS*SS);
    long long rem = idx % ((long long)SS*SS);
    float s = 0.f;
    #pragma unroll
    for (int h = 0; h < HH; h++)
        s += probs[(b*HH + h) * (long long)SS*SS + rem];
    out[idx] = s * (1.f/HH);
}

// ---------------- launch ----------------
extern "C" void kernel_launch(void* const* d_in, const int* in_sizes, int n_in,
                              void* d_out, int out_size)
{
    const float* x      = (const float*)d_in[0];
    // d_in[1] = causal_mask (tril logic applied directly in scores epilogue)
    const float* ln1_g  = (const float*)d_in[2];
    const float* ln1_b  = (const float*)d_in[3];
    const float* ln2_g  = (const float*)d_in[4];
    const float* ln2_b  = (const float*)d_in[5];
    const float* w_in   = (const float*)d_in[6];
    const float* b_in   = (const float*)d_in[7];
    const float* w_out  = (const float*)d_in[8];
    const float* b_out  = (const float*)d_in[9];
    const float* w_fc   = (const float*)d_in[10];
    const float* b_fc   = (const float*)d_in[11];
    const float* w_proj = (const float*)d_in[12];
    const float* b_proj = (const float*)d_in[13];

    float* out_x = (float*)d_out;                       // 4M floats
    float* out_w = (float*)d_out + (long long)ROWS*EE;  // 4M floats (att_weights)

    float *h, *qkv, *probs, *att, *x1, *h2, *fc;
    cudaGetSymbolAddress((void**)&h,     g_h);
    cudaGetSymbolAddress((void**)&qkv,   g_qkv);
    cudaGetSymbolAddress((void**)&probs, g_probs);
    cudaGetSymbolAddress((void**)&att,   g_att);
    cudaGetSymbolAddress((void**)&x1,    g_x1);
    cudaGetSymbolAddress((void**)&h2,    g_h2);
    cudaGetSymbolAddress((void**)&fc,    g_fc);

    const long long SSS = (long long)SS*SS;

    // 1) LN1
    ln_kernel<<<ROWS, 256>>>(x, ln1_g, ln1_b, h);

    // 2) QKV: [4096,3072] = h[4096,1024] @ w_in[3072,1024]^T + b_in
    gemm_kernel<true><<<dim3(3*EE/64, ROWS/64, 1), 256>>>(
        h, w_in, qkv, b_in, nullptr,
        ROWS, 3*EE, EE, EE, EE, 3*EE,
        0,0, 0,0, 0,0, 1, 1.f, 0, 0);

    // 3) scores: per (b,h): probs = scale * q @ k^T (+causal)  (M=N=1024, K=64)
    gemm_kernel<true><<<dim3(SS/64, SS/64, BB*HH), 256>>>(
        qkv /*q*/, qkv + EE /*k*/, probs, nullptr, nullptr,
        SS, SS, DH, 3*EE, 3*EE, SS,
        (long long)SS*3*EE, DH,
        (long long)SS*3*EE, DH,
        (long long)HH*SSS, SSS,
        HH, 0.125f, 0, 1);

    // 4) softmax rows = B*H*S
    softmax_kernel<<<BB*HH*SS, 256>>>(probs);

    // 5) att_weights = mean over heads
    attw_kernel<<<(int)((BB*SSS + 255)/256), 256>>>(probs, out_w);

    // 6) att[b,q,h,d] = probs[b,h] @ v[b,:,h,:]   (M=1024, N=64, K=1024)
    gemm_kernel<false><<<dim3(DH/64, SS/64, BB*HH), 256>>>(
        probs, qkv + 2*EE /*v*/, att, nullptr, nullptr,
        SS, DH, SS, SS, 3*EE, EE,
        (long long)HH*SSS, SSS,
        (long long)SS*3*EE, DH,
        (long long)SS*EE, DH,
        HH, 1.f, 0, 0);

    // 7) x1 = x + att @ w_out^T + b_out
    gemm_kernel<true><<<dim3(EE/64, ROWS/64, 1), 256>>>(
        att, w_out, x1, b_out, x,
        ROWS, EE, EE, EE, EE, EE,
        0,0, 0,0, 0,0, 1, 1.f, 0, 0);

    // 8) LN2
    ln_kernel<<<ROWS, 256>>>(x1, ln2_g, ln2_b, h2);

    // 9) fc = gelu(h2 @ w_fc^T + b_fc)   [4096,4096]
    gemm_kernel<true><<<dim3(4*EE/64, ROWS/64, 1), 256>>>(
        h2, w_fc, fc, b_fc, nullptr,
        ROWS, 4*EE, EE, EE, EE, 4*EE,
        0,0, 0,0, 0,0, 1, 1.f, 1, 0);

    // 10) out_x = x1 + fc @ w_proj^T + b_proj   [4096,1024]
    gemm_kernel<true><<<dim3(EE/64, ROWS/64, 1), 256>>>(
        fc, w_proj, out_x, b_proj, x1,
        ROWS, EE, 4*EE, 4*EE, 4*EE, EE,
        0,0, 0,0, 0,0, 1, 1.f, 0, 0);
}

// round 6
// speedup vs baseline: 2.0240x; 2.0240x over previous
#include <cuda_runtime.h>
#include <cuda_bf16.h>
#include <math.h>
#include <stdint.h>

#define BB 4
#define SS 1024
#define EE 1024
#define HH 16
#define DH 64
#define ROWS (BB*SS)
#define LN_EPS 1e-5f

typedef unsigned short u16;
typedef unsigned int   u32;
typedef unsigned long long u64;

// ---------------- scratch (device globals; no allocation allowed) ----------------
__device__ u16 g_h_hi [ROWS*EE],    g_h_lo [ROWS*EE];
__device__ u16 g_qkv_hi[ROWS*3*EE], g_qkv_lo[ROWS*3*EE];
__device__ u16 g_vt_hi[BB*HH*DH*SS], g_vt_lo[BB*HH*DH*SS];
__device__ u16 g_p_hi[(long long)BB*HH*SS*SS], g_p_lo[(long long)BB*HH*SS*SS];
__device__ u16 g_att_hi[ROWS*EE],   g_att_lo[ROWS*EE];
__device__ float g_x1[ROWS*EE];
__device__ u16 g_h2_hi[ROWS*EE],    g_h2_lo[ROWS*EE];
__device__ u16 g_fc_hi[ROWS*4*EE],  g_fc_lo[ROWS*4*EE];
__device__ u16 g_win_hi [3*EE*EE],  g_win_lo [3*EE*EE];
__device__ u16 g_wout_hi[EE*EE],    g_wout_lo[EE*EE];
__device__ u16 g_wfc_hi [4*EE*EE],  g_wfc_lo [4*EE*EE];
__device__ u16 g_wpr_hi [4*EE*EE],  g_wpr_lo [4*EE*EE];

// ---------------- helpers ----------------
__device__ __forceinline__ float us2f(u16 u){ return __uint_as_float(((u32)u) << 16); }
__device__ __forceinline__ u16 f2us(float f){
    __nv_bfloat16 b = __float2bfloat16_rn(f);
    return __bfloat16_as_ushort(b);
}
__device__ __forceinline__ u32 smem_u32(const void* p){
    u32 a; asm("{ .reg .u64 t; cvta.to.shared.u64 t, %1; cvt.u32.u64 %0, t; }" : "=r"(a) : "l"(p));
    return a;
}
__device__ __forceinline__ void cp16(u32 dst, const void* src){
    asm volatile("cp.async.cg.shared.global [%0], [%1], 16;\n" :: "r"(dst), "l"(src));
}
#define CP_COMMIT() asm volatile("cp.async.commit_group;\n" ::: "memory")
#define CP_WAIT0()  asm volatile("cp.async.wait_group 0;\n" ::: "memory")
#define CP_WAIT1()  asm volatile("cp.async.wait_group 1;\n" ::: "memory")

__device__ __forceinline__ void ldmx4(u32& r0, u32& r1, u32& r2, u32& r3, u32 addr){
    asm volatile("ldmatrix.sync.aligned.m8n8.x4.shared.b16 {%0,%1,%2,%3}, [%4];"
        : "=r"(r0),"=r"(r1),"=r"(r2),"=r"(r3) : "r"(addr));
}
__device__ __forceinline__ void ldmx2(u32& r0, u32& r1, u32 addr){
    asm volatile("ldmatrix.sync.aligned.m8n8.x2.shared.b16 {%0,%1}, [%2];"
        : "=r"(r0),"=r"(r1) : "r"(addr));
}
__device__ __forceinline__ void mma16816(float* c, const u32* a, const u32* b){
    asm volatile("mma.sync.aligned.m16n8k16.row.col.f32.bf16.bf16.f32 "
        "{%0,%1,%2,%3}, {%4,%5,%6,%7}, {%8,%9}, {%0,%1,%2,%3};"
        : "+f"(c[0]),"+f"(c[1]),"+f"(c[2]),"+f"(c[3])
        : "r"(a[0]),"r"(a[1]),"r"(a[2]),"r"(a[3]), "r"(b[0]),"r"(b[1]));
}

// flags
#define FLAG_GELU   1
#define FLAG_CAUSAL 2
#define FLAG_CLIPK  4
#define FLAG_SPLIT  8

#define TM 128
#define KT 32
#define LDS_ROW 40          // 32 k-elems + 8 pad (80B row stride)

// ---------------- HMMA bf16x3-split GEMM ----------------
// C = alpha * A·B^T (+bias/+resid/gelu/split).  A [M,K] K-major hi/lo; B [N,K] K-major hi/lo.
template<int TN>
__global__ __launch_bounds__(256, 1)
void mma_gemm(const u16* __restrict__ Ahi, const u16* __restrict__ Alo, int lda,
              long long sAb, long long sAh,
              const u16* __restrict__ Bhi, const u16* __restrict__ Blo, int ldb,
              long long sBb, long long sBh,
              float* __restrict__ Cf, u16* __restrict__ Chi, u16* __restrict__ Clo, int ldc,
              long long sCb, long long sCh,
              const float* __restrict__ bias, const float* __restrict__ resid,
              int K, int Hdiv, float alpha, int flags)
{
    constexpr int WM = (TN == 128) ? 2 : 4;      // warp grid m
    constexpr int WN = 8 / WM;                   // warp grid n
    constexpr int MT = TM / (WM * 16);           // m16 tiles per warp
    constexpr int NT = TN / (WN * 8);            // n8 tiles per warp
    constexpr int OA = TM * LDS_ROW;             // elems per A buf
    constexpr int OB = TN * LDS_ROW;
    constexpr int STG = 2*OA + 2*OB;             // elems per stage (Ahi,Alo,Bhi,Blo)

    int m0 = blockIdx.y * TM;
    int n0 = blockIdx.x * TN;
    if ((flags & FLAG_CAUSAL) && n0 >= m0 + TM) return;   // fully masked tile

    int z  = blockIdx.z;
    int bb = z / Hdiv, hh = z % Hdiv;
    const u16* Ah = Ahi + bb*sAb + hh*sAh + (long long)m0*lda;
    const u16* Al = Alo + bb*sAb + hh*sAh + (long long)m0*lda;
    const u16* Bh = Bhi + bb*sBb + hh*sBh + (long long)n0*ldb;
    const u16* Bl = Blo + bb*sBb + hh*sBh + (long long)n0*ldb;

    int Keff = K;
    if (flags & FLAG_CLIPK) { int lim = m0 + TM; Keff = (lim < K) ? lim : K; }
    int T = Keff / KT;

    extern __shared__ __align__(128) u16 sm[];
    u32 sbase = smem_u32(sm);
    int tid = threadIdx.x;
    int lane = tid & 31, wid = tid >> 5;
    int warp_m = wid / WN, warp_n = wid % WN;

    // ---- stage loader: A rows TM x 32k, B rows TN x 32k, hi+lo, 16B chunks ----
    auto load_tile = [&](int s, int k0){
        u32 base = sbase + s * STG * 2;          // byte offset
        // A: TM*4 chunks per buf
        for (int e = tid; e < TM*4; e += 256) {
            int r = e >> 2, c = e & 3;
            u32 off = (u32)(r*LDS_ROW*2 + c*16);
            long long g = (long long)r*lda + k0 + c*8;
            cp16(base + off,          Ah + g);
            cp16(base + OA*2 + off,   Al + g);
        }
        for (int e = tid; e < TN*4; e += 256) {
            int r = e >> 2, c = e & 3;
            u32 off = (u32)(r*LDS_ROW*2 + c*16);
            long long g = (long long)r*ldb + k0 + c*8;
            cp16(base + 4*OA + off,         Bh + g);   // 4*OA bytes = 2*OA elems
            cp16(base + 4*OA + 2*OB + off,  Bl + g);
        }
    };

    float acc[MT][NT][4];
    #pragma unroll
    for (int i = 0; i < MT; i++)
        #pragma unroll
        for (int j = 0; j < NT; j++)
            #pragma unroll
            for (int q = 0; q < 4; q++) acc[i][j][q] = 0.f;

    load_tile(0, 0); CP_COMMIT();

    for (int t = 0; t < T; ++t) {
        if (t + 1 < T) { load_tile((t+1) & 1, (t+1)*KT); CP_COMMIT(); CP_WAIT1(); }
        else           { CP_WAIT0(); }
        __syncthreads();

        int s = t & 1;
        u32 aHiB = sbase + s*STG*2;
        u32 aLoB = aHiB + OA*2;
        u32 bHiB = aHiB + 4*OA;
        u32 bLoB = bHiB + OB*2;

        #pragma unroll
        for (int ks = 0; ks < 2; ks++) {
            u32 aHi[MT][4], aLo[MT][4], bHi[NT][2], bLo[NT][2];
            // A frags: lane 0-15 rows, lane>>4 selects k-half byte offset
            #pragma unroll
            for (int mt = 0; mt < MT; mt++) {
                int row = warp_m*MT*16 + mt*16 + (lane & 15);
                u32 off = (u32)(row*LDS_ROW*2 + ks*32 + (lane >> 4)*16);
                ldmx4(aHi[mt][0], aHi[mt][1], aHi[mt][2], aHi[mt][3], aHiB + off);
                ldmx4(aLo[mt][0], aLo[mt][1], aLo[mt][2], aLo[mt][3], aLoB + off);
            }
            #pragma unroll
            for (int nt = 0; nt < NT; nt++) {
                int row = warp_n*NT*8 + nt*8 + (lane & 7);
                u32 off = (u32)(row*LDS_ROW*2 + ks*32 + ((lane >> 3) & 1)*16);
                ldmx2(bHi[nt][0], bHi[nt][1], bHiB + off);
                ldmx2(bLo[nt][0], bLo[nt][1], bLoB + off);
            }
            #pragma unroll
            for (int mt = 0; mt < MT; mt++)
                #pragma unroll
                for (int nt = 0; nt < NT; nt++) {
                    mma16816(acc[mt][nt], aHi[mt], bHi[nt]);
                    mma16816(acc[mt][nt], aHi[mt], bLo[nt]);
                    mma16816(acc[mt][nt], aLo[mt], bHi[nt]);
                }
        }
        __syncthreads();
    }

    // ---- epilogue ----
    long long cb = bb*sCb + hh*sCh;
    #pragma unroll
    for (int mt = 0; mt < MT; mt++) {
        #pragma unroll
        for (int nt = 0; nt < NT; nt++) {
            int rr = m0 + warp_m*MT*16 + mt*16 + (lane >> 2);
            int nn = n0 + warp_n*NT*8 + nt*8 + (lane & 3)*2;
            #pragma unroll
            for (int half = 0; half < 2; half++) {
                int m = rr + half*8;
                long long crow = cb + (long long)m*ldc;
                #pragma unroll
                for (int j = 0; j < 2; j++) {
                    int n = nn + j;
                    float v = acc[mt][nt][half*2 + j] * alpha;
                    if (bias)  v += bias[n];
                    if (resid) v += resid[crow + n];
                    if (flags & FLAG_GELU) {
                        float tg = tanhf(0.7978845608028654f * (v + 0.044715f*v*v*v));
                        v = 0.5f * v * (1.f + tg);
                    }
                    if (flags & FLAG_SPLIT) {
                        u16 hi = f2us(v);
                        Chi[crow + n] = hi;
                        Clo[crow + n] = f2us(v - us2f(hi));
                    } else {
                        Cf[crow + n] = v;
                    }
                }
            }
        }
    }
}

// ---------------- LayerNorm -> bf16 split ----------------
__global__ void ln_split_kernel(const float* __restrict__ x,
                                const float* __restrict__ g,
                                const float* __restrict__ b,
                                u16* __restrict__ ohi, u16* __restrict__ olo)
{
    long long row = blockIdx.x;
    const float* xr = x + row * EE;
    __shared__ float red[256];
    int tid = threadIdx.x;

    float s = 0.f;
    for (int c = tid; c < EE; c += 256) s += xr[c];
    red[tid] = s; __syncthreads();
    for (int st = 128; st > 0; st >>= 1){ if (tid < st) red[tid] += red[tid+st]; __syncthreads(); }
    float mu = red[0] * (1.f/EE); __syncthreads();

    float v = 0.f;
    for (int c = tid; c < EE; c += 256){ float d = xr[c]-mu; v += d*d; }
    red[tid] = v; __syncthreads();
    for (int st = 128; st > 0; st >>= 1){ if (tid < st) red[tid] += red[tid+st]; __syncthreads(); }
    float inv = rsqrtf(red[0]*(1.f/EE) + LN_EPS); __syncthreads();

    for (int c = tid; c < EE; c += 256) {
        float o = (xr[c]-mu)*inv*g[c] + b[c];
        u16 hi = f2us(o);
        ohi[row*EE + c] = hi;
        olo[row*EE + c] = f2us(o - us2f(hi));
    }
}

// ---------------- split f32 -> bf16 hi/lo ----------------
__global__ void split_kernel(const float* __restrict__ src, u16* __restrict__ hi,
                             u16* __restrict__ lo, long long n)
{
    long long i = ((long long)blockIdx.x * 256 + threadIdx.x) * 4;
    if (i >= n) return;
    float4 v = *reinterpret_cast<const float4*>(src + i);
    float vv[4] = {v.x, v.y, v.z, v.w};
    u16 h[4], l[4];
    #pragma unroll
    for (int j = 0; j < 4; j++){ h[j] = f2us(vv[j]); l[j] = f2us(vv[j] - us2f(h[j])); }
    *reinterpret_cast<u64*>(hi + i) = *(u64*)h;
    *reinterpret_cast<u64*>(lo + i) = *(u64*)l;
}

// ---------------- transpose V: qkv[b,s, 2E + h*64 + d] -> vt[(b,h), d, s] ----------------
__global__ void transpose_v(const u16* __restrict__ qh, const u16* __restrict__ ql,
                            u16* __restrict__ vth, u16* __restrict__ vtl)
{
    __shared__ u16 th[32][33], tl[32][33];
    int bh = blockIdx.z; int b = bh >> 4, h = bh & 15;
    int s0 = blockIdx.x * 32, d0 = blockIdx.y * 32;
    int tx = threadIdx.x, ty = threadIdx.y;
    #pragma unroll
    for (int i = 0; i < 4; i++) {
        int s = s0 + ty + i*8;
        long long src = ((long long)(b*SS + s))*(3*EE) + 2*EE + h*DH + d0 + tx;
        th[ty + i*8][tx] = qh[src];
        tl[ty + i*8][tx] = ql[src];
    }
    __syncthreads();
    #pragma unroll
    for (int i = 0; i < 4; i++) {
        int d = d0 + ty + i*8;
        long long dst = ((long long)(bh*DH + d))*SS + s0 + tx;
        vth[dst] = th[tx][ty + i*8];
        vtl[dst] = tl[tx][ty + i*8];
    }
}

// ---------------- causal softmax on bf16-split scores, in place ----------------
__global__ void softmax_split(u16* __restrict__ ph, u16* __restrict__ pl)
{
    int r = blockIdx.x;               // (b*HH + h)*SS + q
    int q = r & (SS-1);
    long long base = (long long)r * SS;
    __shared__ float row[SS];
    __shared__ float red[256];
    int tid = threadIdx.x;

    float mx = -1e30f;
    for (int c = tid; c < SS; c += 256) {
        float v = (c <= q) ? (us2f(ph[base+c]) + us2f(pl[base+c])) : -1e30f;
        row[c] = v;
        mx = fmaxf(mx, v);
    }
    red[tid] = mx; __syncthreads();
    for (int st = 128; st > 0; st >>= 1){ if (tid < st) red[tid] = fmaxf(red[tid], red[tid+st]); __syncthreads(); }
    mx = red[0]; __syncthreads();

    float sum = 0.f;
    for (int c = tid; c < SS; c += 256) {
        if (c <= q){ float e = __expf(row[c]-mx); row[c] = e; sum += e; }
    }
    red[tid] = sum; __syncthreads();
    for (int st = 128; st > 0; st >>= 1){ if (tid < st) red[tid] += red[tid+st]; __syncthreads(); }
    float inv = 1.f / red[0]; __syncthreads();

    for (int c = tid; c < SS; c += 256) {
        float p = (c <= q) ? row[c]*inv : 0.f;
        u16 hi = f2us(p);
        ph[base+c] = hi;
        pl[base+c] = f2us(p - us2f(hi));
    }
}

// ---------------- att_weights = mean over heads ----------------
__global__ void attw_kernel(const u16* __restrict__ ph, const u16* __restrict__ pl,
                            float* __restrict__ out)
{
    long long idx = (long long)blockIdx.x * 256 + threadIdx.x;
    if (idx >= (long long)BB*SS*SS) return;
    long long b   = idx >> 20;
    long long rem = idx & ((1<<20)-1);
    float s = 0.f;
    #pragma unroll
    for (int h = 0; h < HH; h++) {
        long long o = ((b*HH + h) << 20) + rem;
        s += us2f(ph[o]) + us2f(pl[o]);
    }
    out[idx] = s * (1.f/HH);
}

// ---------------- launch ----------------
extern "C" void kernel_launch(void* const* d_in, const int* in_sizes, int n_in,
                              void* d_out, int out_size)
{
    const float* x      = (const float*)d_in[0];
    const float* ln1_g  = (const float*)d_in[2];
    const float* ln1_b  = (const float*)d_in[3];
    const float* ln2_g  = (const float*)d_in[4];
    const float* ln2_b  = (const float*)d_in[5];
    const float* w_in   = (const float*)d_in[6];
    const float* b_in   = (const float*)d_in[7];
    const float* w_out  = (const float*)d_in[8];
    const float* b_out  = (const float*)d_in[9];
    const float* w_fc   = (const float*)d_in[10];
    const float* b_fc   = (const float*)d_in[11];
    const float* w_proj = (const float*)d_in[12];
    const float* b_proj = (const float*)d_in[13];

    float* out_x = (float*)d_out;
    float* out_w = (float*)d_out + (long long)ROWS*EE;

    u16 *h_hi,*h_lo,*qkv_hi,*qkv_lo,*vt_hi,*vt_lo,*p_hi,*p_lo,*att_hi,*att_lo,*h2_hi,*h2_lo,*fc_hi,*fc_lo;
    u16 *win_hi,*win_lo,*wout_hi,*wout_lo,*wfc_hi,*wfc_lo,*wpr_hi,*wpr_lo;
    float *x1;
    cudaGetSymbolAddress((void**)&h_hi, g_h_hi);     cudaGetSymbolAddress((void**)&h_lo, g_h_lo);
    cudaGetSymbolAddress((void**)&qkv_hi, g_qkv_hi); cudaGetSymbolAddress((void**)&qkv_lo, g_qkv_lo);
    cudaGetSymbolAddress((void**)&vt_hi, g_vt_hi);   cudaGetSymbolAddress((void**)&vt_lo, g_vt_lo);
    cudaGetSymbolAddress((void**)&p_hi, g_p_hi);     cudaGetSymbolAddress((void**)&p_lo, g_p_lo);
    cudaGetSymbolAddress((void**)&att_hi, g_att_hi); cudaGetSymbolAddress((void**)&att_lo, g_att_lo);
    cudaGetSymbolAddress((void**)&x1, g_x1);
    cudaGetSymbolAddress((void**)&h2_hi, g_h2_hi);   cudaGetSymbolAddress((void**)&h2_lo, g_h2_lo);
    cudaGetSymbolAddress((void**)&fc_hi, g_fc_hi);   cudaGetSymbolAddress((void**)&fc_lo, g_fc_lo);
    cudaGetSymbolAddress((void**)&win_hi, g_win_hi); cudaGetSymbolAddress((void**)&win_lo, g_win_lo);
    cudaGetSymbolAddress((void**)&wout_hi, g_wout_hi); cudaGetSymbolAddress((void**)&wout_lo, g_wout_lo);
    cudaGetSymbolAddress((void**)&wfc_hi, g_wfc_hi); cudaGetSymbolAddress((void**)&wfc_lo, g_wfc_lo);
    cudaGetSymbolAddress((void**)&wpr_hi, g_wpr_hi); cudaGetSymbolAddress((void**)&wpr_lo, g_wpr_lo);

    // dynamic smem: 2 stages * (2*TM + 2*TN) * 40 elems * 2B
    const int SM128 = 2 * (2*TM*40 + 2*128*40) * 2;   // 81920
    const int SM64  = 2 * (2*TM*40 + 2*64*40) * 2;    // 61440
    cudaFuncSetAttribute(mma_gemm<128>, cudaFuncAttributeMaxDynamicSharedMemorySize, SM128);
    cudaFuncSetAttribute(mma_gemm<64>,  cudaFuncAttributeMaxDynamicSharedMemorySize, SM64);

    const long long SSS = (long long)SS*SS;

    // 0) split weights
    split_kernel<<<3*EE*EE/4/256, 256>>>(w_in,   win_hi, win_lo, 3*EE*EE);
    split_kernel<<<EE*EE/4/256,   256>>>(w_out,  wout_hi, wout_lo, EE*EE);
    split_kernel<<<4*EE*EE/4/256, 256>>>(w_fc,   wfc_hi, wfc_lo, 4*EE*EE);
    split_kernel<<<4*EE*EE/4/256, 256>>>(w_proj, wpr_hi, wpr_lo, 4*EE*EE);

    // 1) LN1 -> split
    ln_split_kernel<<<ROWS, 256>>>(x, ln1_g, ln1_b, h_hi, h_lo);

    // 2) QKV = h @ w_in^T + b_in -> split
    mma_gemm<128><<<dim3(24, 32, 1), 256, SM128>>>(
        h_hi, h_lo, EE, 0, 0,
        win_hi, win_lo, EE, 0, 0,
        nullptr, qkv_hi, qkv_lo, 3*EE, 0, 0,
        b_in, nullptr, EE, 1, 1.f, FLAG_SPLIT);

    // 3) V transpose
    transpose_v<<<dim3(SS/32, DH/32, BB*HH), dim3(32,8)>>>(qkv_hi, qkv_lo, vt_hi, vt_lo);

    // 4) scores = 0.125 * q @ k^T -> split (fully-masked tiles skipped)
    mma_gemm<128><<<dim3(8, 8, BB*HH), 256, SM128>>>(
        qkv_hi, qkv_lo, 3*EE, (long long)SS*3*EE, DH,
        qkv_hi + EE, qkv_lo + EE, 3*EE, (long long)SS*3*EE, DH,
        nullptr, p_hi, p_lo, SS, (long long)HH*SSS, SSS,
        nullptr, nullptr, DH, HH, 0.125f, FLAG_CAUSAL | FLAG_SPLIT);

    // 5) softmax (causal, in-place on split)
    softmax_split<<<BB*HH*SS, 256>>>(p_hi, p_lo);

    // 6) att_weights
    attw_kernel<<<(int)((BB*SSS + 255)/256), 256>>>(p_hi, p_lo, out_w);

    // 7) att = P @ V^T (vt is [d, s] K-major), K clipped causally -> split
    mma_gemm<64><<<dim3(1, 8, BB*HH), 256, SM64>>>(
        p_hi, p_lo, SS, (long long)HH*SSS, SSS,
        vt_hi, vt_lo, SS, (long long)HH*DH*SS, (long long)DH*SS,
        nullptr, att_hi, att_lo, EE, (long long)SS*EE, DH,
        nullptr, nullptr, SS, HH, 1.f, FLAG_CLIPK | FLAG_SPLIT);

    // 8) x1 = x + att @ w_out^T + b_out (f32)
    mma_gemm<128><<<dim3(8, 32, 1), 256, SM128>>>(
        att_hi, att_lo, EE, 0, 0,
        wout_hi, wout_lo, EE, 0, 0,
        x1, nullptr, nullptr, EE, 0, 0,
        b_out, x, EE, 1, 1.f, 0);

    // 9) LN2 -> split
    ln_split_kernel<<<ROWS, 256>>>(x1, ln2_g, ln2_b, h2_hi, h2_lo);

    // 10) fc = gelu(h2 @ w_fc^T + b_fc) -> split
    mma_gemm<128><<<dim3(32, 32, 1), 256, SM128>>>(
        h2_hi, h2_lo, EE, 0, 0,
        wfc_hi, wfc_lo, EE, 0, 0,
        nullptr, fc_hi, fc_lo, 4*EE, 0, 0,
        b_fc, nullptr, EE, 1, 1.f, FLAG_SPLIT | FLAG_GELU);

    // 11) out_x = x1 + fc @ w_proj^T + b_proj (f32)
    mma_gemm<128><<<dim3(8, 32, 1), 256, SM128>>>(
        fc_hi, fc_lo, 4*EE, 0, 0,
        wpr_hi, wpr_lo, 4*EE, 0, 0,
        out_x, nullptr, nullptr, EE, 0, 0,
        b_proj, x1, 4*EE, 1, 1.f, 0);
}

// round 7
// speedup vs baseline: 2.5255x; 1.2478x over previous
#include <cuda_runtime.h>
#include <cuda_bf16.h>
#include <math.h>
#include <stdint.h>

#define BB 4
#define SS 1024
#define EE 1024
#define HH 16
#define DH 64
#define ROWS (BB*SS)
#define LN_EPS 1e-5f

typedef unsigned short u16;
typedef unsigned int   u32;
typedef unsigned long long u64;

// ---------------- scratch (device globals; no allocation allowed) ----------------
__device__ u16 g_h_hi [ROWS*EE],    g_h_lo [ROWS*EE];
__device__ u16 g_qkv_hi[ROWS*3*EE], g_qkv_lo[ROWS*3*EE];
__device__ u16 g_vt_hi[BB*HH*DH*SS], g_vt_lo[BB*HH*DH*SS];
__device__ u16 g_p_hi[(long long)BB*HH*SS*SS], g_p_lo[(long long)BB*HH*SS*SS];
__device__ u16 g_att_hi[ROWS*EE],   g_att_lo[ROWS*EE];
__device__ float g_x1[ROWS*EE];
__device__ u16 g_h2_hi[ROWS*EE],    g_h2_lo[ROWS*EE];
__device__ u16 g_fc_hi[ROWS*4*EE],  g_fc_lo[ROWS*4*EE];
__device__ u16 g_win_hi [3*EE*EE],  g_win_lo [3*EE*EE];
__device__ u16 g_wout_hi[EE*EE],    g_wout_lo[EE*EE];
__device__ u16 g_wfc_hi [4*EE*EE],  g_wfc_lo [4*EE*EE];
__device__ u16 g_wpr_hi [4*EE*EE],  g_wpr_lo [4*EE*EE];

// ---------------- helpers ----------------
__device__ __forceinline__ float us2f(u16 u){ return __uint_as_float(((u32)u) << 16); }
__device__ __forceinline__ u16 f2us(float f){
    __nv_bfloat16 b = __float2bfloat16_rn(f);
    return __bfloat16_as_ushort(b);
}
__device__ __forceinline__ u32 smem_u32(const void* p){
    u32 a; asm("{ .reg .u64 t; cvta.to.shared.u64 t, %1; cvt.u32.u64 %0, t; }" : "=r"(a) : "l"(p));
    return a;
}
__device__ __forceinline__ void cp16(u32 dst, const void* src){
    asm volatile("cp.async.cg.shared.global [%0], [%1], 16;\n" :: "r"(dst), "l"(src));
}
#define CP_COMMIT() asm volatile("cp.async.commit_group;\n" ::: "memory")
#define CP_WAIT0()  asm volatile("cp.async.wait_group 0;\n" ::: "memory")
#define CP_WAIT1()  asm volatile("cp.async.wait_group 1;\n" ::: "memory")

__device__ __forceinline__ void ldmx4(u32& r0, u32& r1, u32& r2, u32& r3, u32 addr){
    asm volatile("ldmatrix.sync.aligned.m8n8.x4.shared.b16 {%0,%1,%2,%3}, [%4];"
        : "=r"(r0),"=r"(r1),"=r"(r2),"=r"(r3) : "r"(addr));
}
__device__ __forceinline__ void ldmx2(u32& r0, u32& r1, u32 addr){
    asm volatile("ldmatrix.sync.aligned.m8n8.x2.shared.b16 {%0,%1}, [%2];"
        : "=r"(r0),"=r"(r1) : "r"(addr));
}
__device__ __forceinline__ void mma16816(float* c, const u32* a, const u32* b){
    asm volatile("mma.sync.aligned.m16n8k16.row.col.f32.bf16.bf16.f32 "
        "{%0,%1,%2,%3}, {%4,%5,%6,%7}, {%8,%9}, {%0,%1,%2,%3};"
        : "+f"(c[0]),"+f"(c[1]),"+f"(c[2]),"+f"(c[3])
        : "r"(a[0]),"r"(a[1]),"r"(a[2]),"r"(a[3]), "r"(b[0]),"r"(b[1]));
}

// flags
#define FLAG_GELU   1
#define FLAG_CAUSAL 2
#define FLAG_CLIPK  4
#define FLAG_SPLIT  8

#define TM 128
#define KT 64
#define LDS_ROW 72          // 64 k-elems + 8 pad (144B row stride; conflict-free ldmatrix)

// ---------------- HMMA bf16x3-split GEMM ----------------
// C = alpha * A·B^T (+bias/+resid/gelu/split).  A [M,K] K-major hi/lo; B [N,K] K-major hi/lo.
template<int TN>
__global__ __launch_bounds__(256, 1)
void mma_gemm(const u16* __restrict__ Ahi, const u16* __restrict__ Alo, int lda,
              long long sAb, long long sAh,
              const u16* __restrict__ Bhi, const u16* __restrict__ Blo, int ldb,
              long long sBb, long long sBh,
              float* __restrict__ Cf, u16* __restrict__ Chi, u16* __restrict__ Clo, int ldc,
              long long sCb, long long sCh,
              const float* __restrict__ bias, const float* __restrict__ resid,
              int K, int Hdiv, float alpha, int flags)
{
    constexpr int WM = (TN == 128) ? 2 : 4;      // warp grid m
    constexpr int WN = 8 / WM;                   // warp grid n
    constexpr int MT = TM / (WM * 16);           // m16 tiles per warp
    constexpr int NT = TN / (WN * 8);            // n8 tiles per warp
    constexpr int OA = TM * LDS_ROW;             // elems per A buf
    constexpr int OB = TN * LDS_ROW;
    constexpr int STG = 2*OA + 2*OB;             // elems per stage (Ahi,Alo,Bhi,Blo)

    int m0 = blockIdx.y * TM;
    int n0 = blockIdx.x * TN;
    if ((flags & FLAG_CAUSAL) && n0 >= m0 + TM) return;   // fully masked tile

    int z  = blockIdx.z;
    int bb = z / Hdiv, hh = z % Hdiv;
    const u16* Ah = Ahi + bb*sAb + hh*sAh + (long long)m0*lda;
    const u16* Al = Alo + bb*sAb + hh*sAh + (long long)m0*lda;
    const u16* Bh = Bhi + bb*sBb + hh*sBh + (long long)n0*ldb;
    const u16* Bl = Blo + bb*sBb + hh*sBh + (long long)n0*ldb;

    int Keff = K;
    if (flags & FLAG_CLIPK) { int lim = m0 + TM; Keff = (lim < K) ? lim : K; }
    int T = Keff / KT;

    extern __shared__ __align__(128) u16 sm[];
    u32 sbase = smem_u32(sm);
    int tid = threadIdx.x;
    int lane = tid & 31, wid = tid >> 5;
    int warp_m = wid / WN, warp_n = wid % WN;

    // ---- stage loader: A rows TM x 64k, B rows TN x 64k, hi+lo, 16B chunks ----
    auto load_tile = [&](int s, int k0){
        u32 base = sbase + s * STG * 2;          // byte offset
        for (int e = tid; e < TM*8; e += 256) {
            int r = e >> 3, c = e & 7;
            u32 off = (u32)(r*LDS_ROW*2 + c*16);
            long long g = (long long)r*lda + k0 + c*8;
            cp16(base + off,          Ah + g);
            cp16(base + OA*2 + off,   Al + g);
        }
        for (int e = tid; e < TN*8; e += 256) {
            int r = e >> 3, c = e & 7;
            u32 off = (u32)(r*LDS_ROW*2 + c*16);
            long long g = (long long)r*ldb + k0 + c*8;
            cp16(base + 4*OA + off,         Bh + g);
            cp16(base + 4*OA + 2*OB + off,  Bl + g);
        }
    };

    float acc[MT][NT][4];
    #pragma unroll
    for (int i = 0; i < MT; i++)
        #pragma unroll
        for (int j = 0; j < NT; j++)
            #pragma unroll
            for (int q = 0; q < 4; q++) acc[i][j][q] = 0.f;

    load_tile(0, 0); CP_COMMIT();

    for (int t = 0; t < T; ++t) {
        if (t + 1 < T) { load_tile((t+1) & 1, (t+1)*KT); CP_COMMIT(); CP_WAIT1(); }
        else           { CP_WAIT0(); }
        __syncthreads();

        int s = t & 1;
        u32 aHiB = sbase + s*STG*2;
        u32 aLoB = aHiB + OA*2;
        u32 bHiB = aHiB + 4*OA;
        u32 bLoB = bHiB + OB*2;

        #pragma unroll
        for (int ks = 0; ks < 4; ks++) {
            u32 aHi[MT][4], aLo[MT][4], bHi[NT][2], bLo[NT][2];
            #pragma unroll
            for (int mt = 0; mt < MT; mt++) {
                int row = warp_m*MT*16 + mt*16 + (lane & 15);
                u32 off = (u32)(row*LDS_ROW*2 + ks*32 + (lane >> 4)*16);
                ldmx4(aHi[mt][0], aHi[mt][1], aHi[mt][2], aHi[mt][3], aHiB + off);
                ldmx4(aLo[mt][0], aLo[mt][1], aLo[mt][2], aLo[mt][3], aLoB + off);
            }
            #pragma unroll
            for (int nt = 0; nt < NT; nt++) {
                int row = warp_n*NT*8 + nt*8 + (lane & 7);
                u32 off = (u32)(row*LDS_ROW*2 + ks*32 + ((lane >> 3) & 1)*16);
                ldmx2(bHi[nt][0], bHi[nt][1], bHiB + off);
                ldmx2(bLo[nt][0], bLo[nt][1], bLoB + off);
            }
            #pragma unroll
            for (int mt = 0; mt < MT; mt++)
                #pragma unroll
                for (int nt = 0; nt < NT; nt++) {
                    mma16816(acc[mt][nt], aHi[mt], bHi[nt]);
                    mma16816(acc[mt][nt], aHi[mt], bLo[nt]);
                    mma16816(acc[mt][nt], aLo[mt], bHi[nt]);
                }
        }
        __syncthreads();
    }

    // ---- epilogue (packed stores: lanes own (n, n+1) pairs) ----
    long long cb = bb*sCb + hh*sCh;
    #pragma unroll
    for (int mt = 0; mt < MT; mt++) {
        #pragma unroll
        for (int nt = 0; nt < NT; nt++) {
            int rr = m0 + warp_m*MT*16 + mt*16 + (lane >> 2);
            int nn = n0 + warp_n*NT*8 + nt*8 + (lane & 3)*2;
            #pragma unroll
            for (int half = 0; half < 2; half++) {
                int m = rr + half*8;
                long long crow = cb + (long long)m*ldc;
                float v[2];
                #pragma unroll
                for (int j = 0; j < 2; j++) {
                    float vv = acc[mt][nt][half*2 + j] * alpha;
                    int n = nn + j;
                    if (bias)  vv += bias[n];
                    if (resid) vv += resid[crow + n];
                    if (flags & FLAG_GELU) {
                        float tg = tanhf(0.7978845608028654f * (vv + 0.044715f*vv*vv*vv));
                        vv = 0.5f * vv * (1.f + tg);
                    }
                    v[j] = vv;
                }
                if (flags & FLAG_SPLIT) {
                    u16 h0 = f2us(v[0]), h1 = f2us(v[1]);
                    u16 l0 = f2us(v[0] - us2f(h0)), l1 = f2us(v[1] - us2f(h1));
                    *reinterpret_cast<u32*>(Chi + crow + nn) = (u32)h0 | ((u32)h1 << 16);
                    *reinterpret_cast<u32*>(Clo + crow + nn) = (u32)l0 | ((u32)l1 << 16);
                } else {
                    *reinterpret_cast<float2*>(Cf + crow + nn) = make_float2(v[0], v[1]);
                }
            }
        }
    }
}

// ---------------- LayerNorm -> bf16 split ----------------
__global__ void ln_split_kernel(const float* __restrict__ x,
                                const float* __restrict__ g,
                                const float* __restrict__ b,
                                u16* __restrict__ ohi, u16* __restrict__ olo)
{
    long long row = blockIdx.x;
    const float* xr = x + row * EE;
    __shared__ float red[256];
    int tid = threadIdx.x;

    float s = 0.f;
    for (int c = tid; c < EE; c += 256) s += xr[c];
    red[tid] = s; __syncthreads();
    for (int st = 128; st > 0; st >>= 1){ if (tid < st) red[tid] += red[tid+st]; __syncthreads(); }
    float mu = red[0] * (1.f/EE); __syncthreads();

    float v = 0.f;
    for (int c = tid; c < EE; c += 256){ float d = xr[c]-mu; v += d*d; }
    red[tid] = v; __syncthreads();
    for (int st = 128; st > 0; st >>= 1){ if (tid < st) red[tid] += red[tid+st]; __syncthreads(); }
    float inv = rsqrtf(red[0]*(1.f/EE) + LN_EPS); __syncthreads();

    for (int c = tid; c < EE; c += 256) {
        float o = (xr[c]-mu)*inv*g[c] + b[c];
        u16 hi = f2us(o);
        ohi[row*EE + c] = hi;
        olo[row*EE + c] = f2us(o - us2f(hi));
    }
}

// ---------------- split f32 -> bf16 hi/lo ----------------
__global__ void split_kernel(const float* __restrict__ src, u16* __restrict__ hi,
                             u16* __restrict__ lo, long long n)
{
    long long i = ((long long)blockIdx.x * 256 + threadIdx.x) * 4;
    if (i >= n) return;
    float4 v = *reinterpret_cast<const float4*>(src + i);
    float vv[4] = {v.x, v.y, v.z, v.w};
    u16 h[4], l[4];
    #pragma unroll
    for (int j = 0; j < 4; j++){ h[j] = f2us(vv[j]); l[j] = f2us(vv[j] - us2f(h[j])); }
    *reinterpret_cast<u64*>(hi + i) = *(u64*)h;
    *reinterpret_cast<u64*>(lo + i) = *(u64*)l;
}

// ---------------- transpose V: qkv[b,s, 2E + h*64 + d] -> vt[(b,h), d, s] ----------------
__global__ void transpose_v(const u16* __restrict__ qh, const u16* __restrict__ ql,
                            u16* __restrict__ vth, u16* __restrict__ vtl)
{
    __shared__ u16 th[32][33], tl[32][33];
    int bh = blockIdx.z; int b = bh >> 4, h = bh & 15;
    int s0 = blockIdx.x * 32, d0 = blockIdx.y * 32;
    int tx = threadIdx.x, ty = threadIdx.y;
    #pragma unroll
    for (int i = 0; i < 4; i++) {
        int s = s0 + ty + i*8;
        long long src = ((long long)(b*SS + s))*(3*EE) + 2*EE + h*DH + d0 + tx;
        th[ty + i*8][tx] = qh[src];
        tl[ty + i*8][tx] = ql[src];
    }
    __syncthreads();
    #pragma unroll
    for (int i = 0; i < 4; i++) {
        int d = d0 + ty + i*8;
        long long dst = ((long long)(bh*DH + d))*SS + s0 + tx;
        vth[dst] = th[tx][ty + i*8];
        vtl[dst] = tl[tx][ty + i*8];
    }
}

// ---------------- causal softmax on bf16-split scores, in place ----------------
__global__ void softmax_split(u16* __restrict__ ph, u16* __restrict__ pl)
{
    int r = blockIdx.x;               // (b*HH + h)*SS + q
    int q = r & (SS-1);
    long long base = (long long)r * SS;
    __shared__ float row[SS];
    __shared__ float red[256];
    int tid = threadIdx.x;

    float mx = -1e30f;
    for (int c = tid; c < SS; c += 256) {
        float v = (c <= q) ? (us2f(ph[base+c]) + us2f(pl[base+c])) : -1e30f;
        row[c] = v;
        mx = fmaxf(mx, v);
    }
    red[tid] = mx; __syncthreads();
    for (int st = 128; st > 0; st >>= 1){ if (tid < st) red[tid] = fmaxf(red[tid], red[tid+st]); __syncthreads(); }
    mx = red[0]; __syncthreads();

    float sum = 0.f;
    for (int c = tid; c < SS; c += 256) {
        if (c <= q){ float e = __expf(row[c]-mx); row[c] = e; sum += e; }
    }
    red[tid] = sum; __syncthreads();
    for (int st = 128; st > 0; st >>= 1){ if (tid < st) red[tid] += red[tid+st]; __syncthreads(); }
    float inv = 1.f / red[0]; __syncthreads();

    for (int c = tid; c < SS; c += 256) {
        float p = (c <= q) ? row[c]*inv : 0.f;
        u16 hi = f2us(p);
        ph[base+c] = hi;
        pl[base+c] = f2us(p - us2f(hi));
    }
}

// ---------------- att_weights = mean over heads (causal skip) ----------------
__global__ void attw_kernel(const u16* __restrict__ ph, const u16* __restrict__ pl,
                            float* __restrict__ out)
{
    long long idx = (long long)blockIdx.x * 256 + threadIdx.x;
    if (idx >= (long long)BB*SS*SS) return;
    long long b   = idx >> 20;
    long long rem = idx & ((1<<20)-1);
    int q = (int)(rem >> 10), k = (int)(rem & (SS-1));
    if (k > q) { out[idx] = 0.f; return; }     // exact zeros above diagonal
    float s = 0.f;
    #pragma unroll
    for (int h = 0; h < HH; h++) {
        long long o = ((b*HH + h) << 20) + rem;
        s += us2f(ph[o]) + us2f(pl[o]);
    }
    out[idx] = s * (1.f/HH);
}

// ---------------- launch ----------------
extern "C" void kernel_launch(void* const* d_in, const int* in_sizes, int n_in,
                              void* d_out, int out_size)
{
    const float* x      = (const float*)d_in[0];
    const float* ln1_g  = (const float*)d_in[2];
    const float* ln1_b  = (const float*)d_in[3];
    const float* ln2_g  = (const float*)d_in[4];
    const float* ln2_b  = (const float*)d_in[5];
    const float* w_in   = (const float*)d_in[6];
    const float* b_in   = (const float*)d_in[7];
    const float* w_out  = (const float*)d_in[8];
    const float* b_out  = (const float*)d_in[9];
    const float* w_fc   = (const float*)d_in[10];
    const float* b_fc   = (const float*)d_in[11];
    const float* w_proj = (const float*)d_in[12];
    const float* b_proj = (const float*)d_in[13];

    float* out_x = (float*)d_out;
    float* out_w = (float*)d_out + (long long)ROWS*EE;

    u16 *h_hi,*h_lo,*qkv_hi,*qkv_lo,*vt_hi,*vt_lo,*p_hi,*p_lo,*att_hi,*att_lo,*h2_hi,*h2_lo,*fc_hi,*fc_lo;
    u16 *win_hi,*win_lo,*wout_hi,*wout_lo,*wfc_hi,*wfc_lo,*wpr_hi,*wpr_lo;
    float *x1;
    cudaGetSymbolAddress((void**)&h_hi, g_h_hi);     cudaGetSymbolAddress((void**)&h_lo, g_h_lo);
    cudaGetSymbolAddress((void**)&qkv_hi, g_qkv_hi); cudaGetSymbolAddress((void**)&qkv_lo, g_qkv_lo);
    cudaGetSymbolAddress((void**)&vt_hi, g_vt_hi);   cudaGetSymbolAddress((void**)&vt_lo, g_vt_lo);
    cudaGetSymbolAddress((void**)&p_hi, g_p_hi);     cudaGetSymbolAddress((void**)&p_lo, g_p_lo);
    cudaGetSymbolAddress((void**)&att_hi, g_att_hi); cudaGetSymbolAddress((void**)&att_lo, g_att_lo);
    cudaGetSymbolAddress((void**)&x1, g_x1);
    cudaGetSymbolAddress((void**)&h2_hi, g_h2_hi);   cudaGetSymbolAddress((void**)&h2_lo, g_h2_lo);
    cudaGetSymbolAddress((void**)&fc_hi, g_fc_hi);   cudaGetSymbolAddress((void**)&fc_lo, g_fc_lo);
    cudaGetSymbolAddress((void**)&win_hi, g_win_hi); cudaGetSymbolAddress((void**)&win_lo, g_win_lo);
    cudaGetSymbolAddress((void**)&wout_hi, g_wout_hi); cudaGetSymbolAddress((void**)&wout_lo, g_wout_lo);
    cudaGetSymbolAddress((void**)&wfc_hi, g_wfc_hi); cudaGetSymbolAddress((void**)&wfc_lo, g_wfc_lo);
    cudaGetSymbolAddress((void**)&wpr_hi, g_wpr_hi); cudaGetSymbolAddress((void**)&wpr_lo, g_wpr_lo);

    // dynamic smem: 2 stages * (2*TM + 2*TN) rows * 72 elems * 2B
    const int SM128 = 2 * (2*TM*LDS_ROW + 2*128*LDS_ROW) * 2;   // 147456
    const int SM64  = 2 * (2*TM*LDS_ROW + 2*64*LDS_ROW) * 2;    // 110592
    cudaFuncSetAttribute(mma_gemm<128>, cudaFuncAttributeMaxDynamicSharedMemorySize, SM128);
    cudaFuncSetAttribute(mma_gemm<64>,  cudaFuncAttributeMaxDynamicSharedMemorySize, SM64);

    const long long SSS = (long long)SS*SS;

    // 0) split weights
    split_kernel<<<3*EE*EE/4/256, 256>>>(w_in,   win_hi, win_lo, 3*EE*EE);
    split_kernel<<<EE*EE/4/256,   256>>>(w_out,  wout_hi, wout_lo, EE*EE);
    split_kernel<<<4*EE*EE/4/256, 256>>>(w_fc,   wfc_hi, wfc_lo, 4*EE*EE);
    split_kernel<<<4*EE*EE/4/256, 256>>>(w_proj, wpr_hi, wpr_lo, 4*EE*EE);

    // 1) LN1 -> split
    ln_split_kernel<<<ROWS, 256>>>(x, ln1_g, ln1_b, h_hi, h_lo);

    // 2) QKV = h @ w_in^T + b_in -> split
    mma_gemm<128><<<dim3(24, 32, 1), 256, SM128>>>(
        h_hi, h_lo, EE, 0, 0,
        win_hi, win_lo, EE, 0, 0,
        nullptr, qkv_hi, qkv_lo, 3*EE, 0, 0,
        b_in, nullptr, EE, 1, 1.f, FLAG_SPLIT);

    // 3) V transpose
    transpose_v<<<dim3(SS/32, DH/32, BB*HH), dim3(32,8)>>>(qkv_hi, qkv_lo, vt_hi, vt_lo);

    // 4) scores = 0.125 * q @ k^T -> split (fully-masked tiles skipped)
    mma_gemm<128><<<dim3(8, 8, BB*HH), 256, SM128>>>(
        qkv_hi, qkv_lo, 3*EE, (long long)SS*3*EE, DH,
        qkv_hi + EE, qkv_lo + EE, 3*EE, (long long)SS*3*EE, DH,
        nullptr, p_hi, p_lo, SS, (long long)HH*SSS, SSS,
        nullptr, nullptr, DH, HH, 0.125f, FLAG_CAUSAL | FLAG_SPLIT);

    // 5) softmax (causal, in-place on split)
    softmax_split<<<BB*HH*SS, 256>>>(p_hi, p_lo);

    // 6) att_weights
    attw_kernel<<<(int)((BB*SSS + 255)/256), 256>>>(p_hi, p_lo, out_w);

    // 7) att = P @ V^T (vt is [d, s] K-major), K clipped causally -> split
    mma_gemm<64><<<dim3(1, 8, BB*HH), 256, SM64>>>(
        p_hi, p_lo, SS, (long long)HH*SSS, SSS,
        vt_hi, vt_lo, SS, (long long)HH*DH*SS, (long long)DH*SS,
        nullptr, att_hi, att_lo, EE, (long long)SS*EE, DH,
        nullptr, nullptr, SS, HH, 1.f, FLAG_CLIPK | FLAG_SPLIT);

    // 8) x1 = x + att @ w_out^T + b_out (f32)
    mma_gemm<128><<<dim3(8, 32, 1), 256, SM128>>>(
        att_hi, att_lo, EE, 0, 0,
        wout_hi, wout_lo, EE, 0, 0,
        x1, nullptr, nullptr, EE, 0, 0,
        b_out, x, EE, 1, 1.f, 0);

    // 9) LN2 -> split
    ln_split_kernel<<<ROWS, 256>>>(x1, ln2_g, ln2_b, h2_hi, h2_lo);

    // 10) fc = gelu(h2 @ w_fc^T + b_fc) -> split
    mma_gemm<128><<<dim3(32, 32, 1), 256, SM128>>>(
        h2_hi, h2_lo, EE, 0, 0,
        wfc_hi, wfc_lo, EE, 0, 0,
        nullptr, fc_hi, fc_lo, 4*EE, 0, 0,
        b_fc, nullptr, EE, 1, 1.f, FLAG_SPLIT | FLAG_GELU);

    // 11) out_x = x1 + fc @ w_proj^T + b_proj (f32)
    mma_gemm<128><<<dim3(8, 32, 1), 256, SM128>>>(
        fc_hi, fc_lo, 4*EE, 0, 0,
        wpr_hi, wpr_lo, 4*EE, 0, 0,
        out_x, nullptr, nullptr, EE, 0, 0,
        b_proj, x1, 4*EE, 1, 1.f, 0);
}